// round 6
// baseline (speedup 1.0000x reference)
#include <cuda_runtime.h>
#include <math.h>

#define MPTS 32
#define PPB  8     // 1 pillar per warp, 8 warps/block

// Precomputed constants.
// g_dupA[c][o] = (w, w) pre-duplicated pair for packed f32x2 FMA (channel o)
__device__ float2 g_dupA[4][64];
__device__ float2 g_pW[6][32];   // (W[2t], W[2t+1]) for c in 4..9
__device__ float2 g_pbp[32];     // BN-folded bias pairs
__device__ float2 g_pgb[32];     // gelu(bias) pairs (masked-row contribution)

__device__ __forceinline__ float gelu_exact(float x) {
    return 0.5f * x * (1.0f + erff(x * 0.70710678118654752f));
}

typedef unsigned long long u64;
__device__ __forceinline__ u64 fma2(u64 a, u64 b, u64 c) {
    u64 d; asm("fma.rn.f32x2 %0, %1, %2, %3;" : "=l"(d) : "l"(a), "l"(b), "l"(c));
    return d;
}
__device__ __forceinline__ u64 mul2(u64 a, u64 b) {
    u64 d; asm("mul.rn.f32x2 %0, %1, %2;" : "=l"(d) : "l"(a), "l"(b));
    return d;
}
__device__ __forceinline__ void unpack2(u64 v, float& lo, float& hi) {
    asm("mov.b64 {%0, %1}, %2;" : "=f"(lo), "=f"(hi) : "l"(v));
}

// Fold BN into W; exploit affine structure of augmented channels:
//   x[m,o] = f0*(w0+w4+w7)+f1*(w1+w5+w8)+f2*(w2+w6+w9)+f3*w3
//            - mx*w4-my*w5-mz*w6 - px*w7-py*w8-pz*w9 + bias
__global__ void pfn_precompute(const float* __restrict__ W,
                               const float* __restrict__ gamma,
                               const float* __restrict__ beta,
                               const float* __restrict__ rmean,
                               const float* __restrict__ rvar) {
    int o = threadIdx.x;
    if (o >= 64) return;
    float s  = rsqrtf(rvar[o] + 1e-3f) * gamma[o];
    float bp = beta[o] - rmean[o] * s;
    float w[10];
#pragma unroll
    for (int c = 0; c < 10; c++) w[c] = W[o * 10 + c] * s;
    float A0 = w[0] + w[4] + w[7];
    float A1 = w[1] + w[5] + w[8];
    float A2 = w[2] + w[6] + w[9];
    float A3 = w[3];
    g_dupA[0][o] = make_float2(A0, A0);
    g_dupA[1][o] = make_float2(A1, A1);
    g_dupA[2][o] = make_float2(A2, A2);
    g_dupA[3][o] = make_float2(A3, A3);
    int t = o >> 1, h = o & 1;
#pragma unroll
    for (int c = 0; c < 6; c++) ((float*)&g_pW[c][t])[h] = w[4 + c];
    ((float*)&g_pbp[t])[h] = bp;
    ((float*)&g_pgb[t])[h] = gelu_exact(bp);
}

__global__ __launch_bounds__(PPB * 32, 5)
void pfn_main(const float4* __restrict__ feats,       // [N,32] float4
              const int*    __restrict__ num_points,   // [N]
              const int4*   __restrict__ coors,        // [N] (z,y,x,_)
              float*        __restrict__ out,          // [N,64]
              int N) {
    __shared__ float sdat[PPB][4][MPTS];    // transposed SoA per pillar

    const int lw   = threadIdx.x >> 5;
    const int lane = threadIdx.x & 31;
    const int p    = blockIdx.x * PPB + lw;
    if (p >= N) return;                      // warp-uniform

    const int K = num_points[p];

    // ---- stage: coalesced 512B load per warp ----
    float4 row = feats[(size_t)p * MPTS + lane];

    // mean over ALL 32 raw rows (reference semantics), divided by K
    float sx = row.x, sy = row.y, sz = row.z;
#pragma unroll
    for (int off = 16; off; off >>= 1) {
        sx += __shfl_xor_sync(0xffffffffu, sx, off);
        sy += __shfl_xor_sync(0xffffffffu, sy, off);
        sz += __shfl_xor_sync(0xffffffffu, sz, off);
    }
    const float rK = __frcp_rn((float)K);
    const float mx = sx * rK, my = sy * rK, mz = sz * rK;

    // pad invalid rows with a COPY of row 0 (K>=1): duplicates a valid
    // point's dot value, so max/min over points are unaffected.
    float r0x = __shfl_sync(0xffffffffu, row.x, 0);
    float r0y = __shfl_sync(0xffffffffu, row.y, 0);
    float r0z = __shfl_sync(0xffffffffu, row.z, 0);
    float r0w = __shfl_sync(0xffffffffu, row.w, 0);
    if (lane >= K) { row.x = r0x; row.y = r0y; row.z = r0z; row.w = r0w; }
    sdat[lw][0][lane] = row.x;
    sdat[lw][1][lane] = row.y;
    sdat[lw][2][lane] = row.z;
    sdat[lw][3][lane] = row.w;
    __syncwarp();

    // ---- per-thread constants: channels (2*lane, 2*lane+1) ----
    const u64 a0c0 = *(const u64*)&g_dupA[0][2 * lane];
    const u64 a0c1 = *(const u64*)&g_dupA[0][2 * lane + 1];
    const u64 a1c0 = *(const u64*)&g_dupA[1][2 * lane];
    const u64 a1c1 = *(const u64*)&g_dupA[1][2 * lane + 1];
    const u64 a2c0 = *(const u64*)&g_dupA[2][2 * lane];
    const u64 a2c1 = *(const u64*)&g_dupA[2][2 * lane + 1];
    const u64 a3c0 = *(const u64*)&g_dupA[3][2 * lane];
    const u64 a3c1 = *(const u64*)&g_dupA[3][2 * lane + 1];
    const float2 bp = g_pbp[lane];
    const float2 gb = g_pgb[lane];

    const int4 cr = coors[p];
    // VX=VY=0.2, VZ=4.0; X_OFF=0.1, Y_OFF=-39.9, Z_OFF=-1.0; cols (cz,cy,cx)
    const float px = (float)cr.z * 0.2f + 0.1f;
    const float py = (float)cr.y * 0.2f + (-39.9f);
    const float pz = (float)cr.x * 4.0f + (-1.0f);

    const float2 W4 = g_pW[0][lane], W5 = g_pW[1][lane], W6 = g_pW[2][lane];
    const float2 W7 = g_pW[3][lane], W8 = g_pW[4][lane], W9 = g_pW[5][lane];

    float cst0 = bp.x, cst1 = bp.y;
    cst0 = fmaf(-mx, W4.x, cst0); cst1 = fmaf(-mx, W4.y, cst1);
    cst0 = fmaf(-my, W5.x, cst0); cst1 = fmaf(-my, W5.y, cst1);
    cst0 = fmaf(-mz, W6.x, cst0); cst1 = fmaf(-mz, W6.y, cst1);
    cst0 = fmaf(-px, W7.x, cst0); cst1 = fmaf(-px, W7.y, cst1);
    cst0 = fmaf(-py, W8.x, cst0); cst1 = fmaf(-py, W8.y, cst1);
    cst0 = fmaf(-pz, W9.x, cst0); cst1 = fmaf(-pz, W9.y, cst1);

    // ---- hot loop: both MIN and MAX (cst spread is huge: gelu can be
    // decreasing over the whole dot range, so min is routinely the winner) ----
    const float INF = 3.402823466e38f;
    float mx0a = -INF, mx0b = -INF, mn0a = INF, mn0b = INF;   // channel 0
    float mx1a = -INF, mx1b = -INF, mn1a = INF, mn1b = INF;   // channel 1

    const int T = (K + 3) >> 2;
#pragma unroll 2
    for (int i = 0; i < T; i++) {
        ulonglong2 X  = *(const ulonglong2*)&sdat[lw][0][4 * i];
        ulonglong2 Y  = *(const ulonglong2*)&sdat[lw][1][4 * i];
        ulonglong2 Z  = *(const ulonglong2*)&sdat[lw][2][4 * i];
        ulonglong2 Wv = *(const ulonglong2*)&sdat[lw][3][4 * i];

        u64 d0a = fma2(X.x, a0c0, fma2(Y.x, a1c0, fma2(Z.x, a2c0, mul2(Wv.x, a3c0))));
        u64 d0b = fma2(X.y, a0c0, fma2(Y.y, a1c0, fma2(Z.y, a2c0, mul2(Wv.y, a3c0))));
        u64 d1a = fma2(X.x, a0c1, fma2(Y.x, a1c1, fma2(Z.x, a2c1, mul2(Wv.x, a3c1))));
        u64 d1b = fma2(X.y, a0c1, fma2(Y.y, a1c1, fma2(Z.y, a2c1, mul2(Wv.y, a3c1))));

        float l, h;
        unpack2(d0a, l, h); mx0a = fmaxf(mx0a, l); mn0a = fminf(mn0a, l);
                            mx0b = fmaxf(mx0b, h); mn0b = fminf(mn0b, h);
        unpack2(d0b, l, h); mx0a = fmaxf(mx0a, l); mn0a = fminf(mn0a, l);
                            mx0b = fmaxf(mx0b, h); mn0b = fminf(mn0b, h);
        unpack2(d1a, l, h); mx1a = fmaxf(mx1a, l); mn1a = fminf(mn1a, l);
                            mx1b = fmaxf(mx1b, h); mn1b = fminf(mn1b, h);
        unpack2(d1b, l, h); mx1a = fmaxf(mx1a, l); mn1a = fminf(mn1a, l);
                            mx1b = fmaxf(mx1b, h); mn1b = fminf(mn1b, h);
    }

    const float b0 = fmaxf(mx0a, mx0b) + cst0;
    const float a0 = fminf(mn0a, mn0b) + cst0;
    const float b1 = fmaxf(mx1a, mx1b) + cst1;
    const float a1 = fminf(mn1a, mn1b) + cst1;

    // gelu unimodal => max over the point set = max(gelu(min), gelu(max)).
    // Straight-line 4x erff: no divergence, shortest live ranges.
    float r0 = fmaxf(gelu_exact(b0), gelu_exact(a0));
    float r1 = fmaxf(gelu_exact(b1), gelu_exact(a1));

    if (K < MPTS) { r0 = fmaxf(r0, gb.x); r1 = fmaxf(r1, gb.y); }

    *(float2*)&out[(size_t)p * 64 + 2 * lane] = make_float2(r0, r1);
}

extern "C" void kernel_launch(void* const* d_in, const int* in_sizes, int n_in,
                              void* d_out, int out_size) {
    const float* features   = (const float*)d_in[0];
    const int*   num_points = (const int*)d_in[1];
    const int*   coors      = (const int*)d_in[2];
    const float* W          = (const float*)d_in[3];
    const float* gamma      = (const float*)d_in[4];
    const float* beta       = (const float*)d_in[5];
    const float* rmean      = (const float*)d_in[6];
    const float* rvar       = (const float*)d_in[7];
    float* out = (float*)d_out;

    const int N = in_sizes[0] / (MPTS * 4);

    pfn_precompute<<<1, 64>>>(W, gamma, beta, rmean, rvar);

    int blocks = (N + PPB - 1) / PPB;
    pfn_main<<<blocks, PPB * 32>>>((const float4*)features, num_points,
                                   (const int4*)coors, out, N);
}

// round 7
// speedup vs baseline: 1.1795x; 1.1795x over previous
#include <cuda_runtime.h>
#include <math.h>

#define MPTS 32
#define PPB  8     // pillars per block, 1 warp per pillar (256 threads)

// Precomputed constants, packed per channel-pair t: (val[2t], val[2t+1])
__device__ float2 g_pA[4][32];   // folded A0..A3 (dot coefficients)
__device__ float2 g_pW[6][32];   // W4..W9 (for mean/center const folding)
__device__ float2 g_pbp[32];     // BN-folded bias
__device__ float2 g_pgb[32];     // gelu(bias) = masked-row contribution

__device__ __forceinline__ float gelu_exact(float x) {
    return 0.5f * x * (1.0f + erff(x * 0.70710678118654752f));
}

// Branchless fast GELU: erf via Abramowitz-Stegun 7.1.26 (|err| < 1.5e-7).
// Tails are exact: exp2(-t*t*L) underflows to 0 => gelu -> x (x>0) / 0 (x<0).
__device__ __forceinline__ float gelu_fast(float x) {
    float t = fabsf(x) * 0.70710678118654752f;
    float kd = fmaf(0.3275911f, t, 1.0f);
    float k;
    asm("rcp.approx.f32 %0, %1;" : "=f"(k) : "f"(kd));
    float p = fmaf(1.061405429f, k, -1.453152027f);
    p = fmaf(p, k, 1.421413741f);
    p = fmaf(p, k, -0.284496736f);
    p = fmaf(p, k, 0.254829592f);
    p = p * k;
    float e = exp2f(-t * t * 1.4426950408889634f);   // exp(-t^2)
    float erf_abs = fmaf(-p, e, 1.0f);                // erf(|x|/sqrt2)
    float erf_x = copysignf(erf_abs, x);
    float hx = 0.5f * x;
    return fmaf(hx, erf_x, hx);                       // 0.5*x*(1+erf)
}

typedef unsigned long long u64;
__device__ __forceinline__ u64 fma2(u64 a, u64 b, u64 c) {
    u64 d; asm("fma.rn.f32x2 %0, %1, %2, %3;" : "=l"(d) : "l"(a), "l"(b), "l"(c));
    return d;
}
__device__ __forceinline__ u64 mul2(u64 a, u64 b) {
    u64 d; asm("mul.rn.f32x2 %0, %1, %2;" : "=l"(d) : "l"(a), "l"(b));
    return d;
}
__device__ __forceinline__ u64 pack2(float lo, float hi) {
    u64 d; asm("mov.b64 %0, {%1, %2};" : "=l"(d) : "f"(lo), "f"(hi));
    return d;
}
__device__ __forceinline__ void unpack2(u64 v, float& lo, float& hi) {
    asm("mov.b64 {%0, %1}, %2;" : "=f"(lo), "=f"(hi) : "l"(v));
}

// Fold BN into W; exploit affine structure of augmented channels:
//   x[m,o] = f0*(w0+w4+w7)+f1*(w1+w5+w8)+f2*(w2+w6+w9)+f3*w3
//            - mx*w4-my*w5-mz*w6 - px*w7-py*w8-pz*w9 + bias
__global__ void pfn_precompute(const float* __restrict__ W,
                               const float* __restrict__ gamma,
                               const float* __restrict__ beta,
                               const float* __restrict__ rmean,
                               const float* __restrict__ rvar) {
    int o = threadIdx.x;
    if (o >= 64) return;
    float s  = rsqrtf(rvar[o] + 1e-3f) * gamma[o];
    float bp = beta[o] - rmean[o] * s;
    float w[10];
#pragma unroll
    for (int c = 0; c < 10; c++) w[c] = W[o * 10 + c] * s;
    int t = o >> 1, h = o & 1;
    ((float*)&g_pA[0][t])[h] = w[0] + w[4] + w[7];
    ((float*)&g_pA[1][t])[h] = w[1] + w[5] + w[8];
    ((float*)&g_pA[2][t])[h] = w[2] + w[6] + w[9];
    ((float*)&g_pA[3][t])[h] = w[3];
#pragma unroll
    for (int c = 0; c < 6; c++) ((float*)&g_pW[c][t])[h] = w[4 + c];
    ((float*)&g_pbp[t])[h] = bp;
    ((float*)&g_pgb[t])[h] = gelu_exact(bp);
}

__global__ __launch_bounds__(PPB * 32)
void pfn_main(const float4* __restrict__ feats,      // [N,32] float4
              const int*    __restrict__ num_points,  // [N]
              const int4*   __restrict__ coors,       // [N] (z,y,x,_)
              float*        __restrict__ out,         // [N,64]
              int N) {
    __shared__ float sdat[PPB][4][MPTS];   // transposed SoA per pillar

    const int lp   = threadIdx.x >> 5;
    const int lane = threadIdx.x & 31;
    const int p    = blockIdx.x * PPB + lp;
    if (p >= N) return;                     // whole warp exits together

    const int K = num_points[p];

    // ---- stage: coalesced 512B row load per warp ----
    float4 row = feats[(size_t)p * MPTS + lane];

    // mean over ALL 32 raw rows (reference sums unmasked garbage too), / K
    float sx = row.x, sy = row.y, sz = row.z;
#pragma unroll
    for (int off = 16; off; off >>= 1) {
        sx += __shfl_xor_sync(0xffffffffu, sx, off);
        sy += __shfl_xor_sync(0xffffffffu, sy, off);
        sz += __shfl_xor_sync(0xffffffffu, sz, off);
    }
    float rK;
    asm("rcp.approx.f32 %0, %1;" : "=f"(rK) : "f"((float)K));
    const float mx = sx * rK, my = sy * rK, mz = sz * rK;

    // pad invalid rows with a COPY of row 0 (K>=1 always): duplicates a valid
    // point's d-value, so min/max are unaffected by padding.
    float r0x = __shfl_sync(0xffffffffu, row.x, 0);
    float r0y = __shfl_sync(0xffffffffu, row.y, 0);
    float r0z = __shfl_sync(0xffffffffu, row.z, 0);
    float r0w = __shfl_sync(0xffffffffu, row.w, 0);
    if (lane >= K) { row.x = r0x; row.y = r0y; row.z = r0z; row.w = r0w; }
    sdat[lp][0][lane] = row.x;
    sdat[lp][1][lane] = row.y;
    sdat[lp][2][lane] = row.z;
    sdat[lp][3][lane] = row.w;
    __syncwarp();

    // ---- per-thread constants: channels (2*lane, 2*lane+1) ----
    const float2 A0 = g_pA[0][lane], A1 = g_pA[1][lane];
    const float2 A2 = g_pA[2][lane], A3 = g_pA[3][lane];
    const float2 W4 = g_pW[0][lane], W5 = g_pW[1][lane], W6 = g_pW[2][lane];
    const float2 W7 = g_pW[3][lane], W8 = g_pW[4][lane], W9 = g_pW[5][lane];
    const float2 bp = g_pbp[lane],   gb = g_pgb[lane];

    const int4 cr = coors[p];
    // VX=VY=0.2, VZ=4.0; X_OFF=0.1, Y_OFF=-39.9, Z_OFF=-1.0; cols (cz,cy,cx)
    const float px = (float)cr.z * 0.2f + 0.1f;
    const float py = (float)cr.y * 0.2f + (-39.9f);
    const float pz = (float)cr.x * 4.0f + (-1.0f);

    float cst0 = bp.x, cst1 = bp.y;
    cst0 = fmaf(-mx, W4.x, cst0); cst1 = fmaf(-mx, W4.y, cst1);
    cst0 = fmaf(-my, W5.x, cst0); cst1 = fmaf(-my, W5.y, cst1);
    cst0 = fmaf(-mz, W6.x, cst0); cst1 = fmaf(-mz, W6.y, cst1);
    cst0 = fmaf(-px, W7.x, cst0); cst1 = fmaf(-px, W7.y, cst1);
    cst0 = fmaf(-py, W8.x, cst0); cst1 = fmaf(-py, W8.y, cst1);
    cst0 = fmaf(-pz, W9.x, cst0); cst1 = fmaf(-pz, W9.y, cst1);

    // duplicated packed coefficients (built once; used every iter)
    const u64 a0c0 = pack2(A0.x, A0.x), a0c1 = pack2(A0.y, A0.y);
    const u64 a1c0 = pack2(A1.x, A1.x), a1c1 = pack2(A1.y, A1.y);
    const u64 a2c0 = pack2(A2.x, A2.x), a2c1 = pack2(A2.y, A2.y);
    const u64 a3c0 = pack2(A3.x, A3.x), a3c1 = pack2(A3.y, A3.y);

    const float INF = 3.402823466e38f;
    float mx0a = -INF, mx0b = -INF, mn0a = INF, mn0b = INF;   // channel 0
    float mx1a = -INF, mx1b = -INF, mn1a = INF, mn1b = INF;   // channel 1

    const int T = (K + 3) >> 2;
#pragma unroll 2
    for (int i = 0; i < T; i++) {
        // 4 points of each component as (m,m+1),(m+2,m+3) f32x2 pairs
        ulonglong2 X  = *(const ulonglong2*)&sdat[lp][0][4 * i];
        ulonglong2 Y  = *(const ulonglong2*)&sdat[lp][1][4 * i];
        ulonglong2 Z  = *(const ulonglong2*)&sdat[lp][2][4 * i];
        ulonglong2 Wv = *(const ulonglong2*)&sdat[lp][3][4 * i];

        // channel 0
        u64 d0a = fma2(X.x, a0c0, fma2(Y.x, a1c0, fma2(Z.x, a2c0, mul2(Wv.x, a3c0))));
        u64 d0b = fma2(X.y, a0c0, fma2(Y.y, a1c0, fma2(Z.y, a2c0, mul2(Wv.y, a3c0))));
        // channel 1
        u64 d1a = fma2(X.x, a0c1, fma2(Y.x, a1c1, fma2(Z.x, a2c1, mul2(Wv.x, a3c1))));
        u64 d1b = fma2(X.y, a0c1, fma2(Y.y, a1c1, fma2(Z.y, a2c1, mul2(Wv.y, a3c1))));

        float l, h;
        unpack2(d0a, l, h); mx0a = fmaxf(mx0a, l); mn0a = fminf(mn0a, l);
                            mx0b = fmaxf(mx0b, h); mn0b = fminf(mn0b, h);
        unpack2(d0b, l, h); mx0a = fmaxf(mx0a, l); mn0a = fminf(mn0a, l);
                            mx0b = fmaxf(mx0b, h); mn0b = fminf(mn0b, h);
        unpack2(d1a, l, h); mx1a = fmaxf(mx1a, l); mn1a = fminf(mn1a, l);
                            mx1b = fmaxf(mx1b, h); mn1b = fminf(mn1b, h);
        unpack2(d1b, l, h); mx1a = fmaxf(mx1a, l); mn1a = fminf(mn1a, l);
                            mx1b = fmaxf(mx1b, h); mn1b = fminf(mn1b, h);
    }

    const float dmax0 = fmaxf(mx0a, mx0b), dmin0 = fminf(mn0a, mn0b);
    const float dmax1 = fmaxf(mx1a, mx1b), dmin1 = fminf(mn1a, mn1b);

    // gelu unimodal => max over gelu = max(gelu(min), gelu(max));
    // masked rows contribute exactly gelu(bias).
    float r0 = fmaxf(gelu_fast(dmax0 + cst0), gelu_fast(dmin0 + cst0));
    float r1 = fmaxf(gelu_fast(dmax1 + cst1), gelu_fast(dmin1 + cst1));
    if (K < MPTS) { r0 = fmaxf(r0, gb.x); r1 = fmaxf(r1, gb.y); }

    *(float2*)&out[(size_t)p * 64 + 2 * lane] = make_float2(r0, r1);
}

extern "C" void kernel_launch(void* const* d_in, const int* in_sizes, int n_in,
                              void* d_out, int out_size) {
    const float* features   = (const float*)d_in[0];
    const int*   num_points = (const int*)d_in[1];
    const int*   coors      = (const int*)d_in[2];
    const float* W          = (const float*)d_in[3];
    const float* gamma      = (const float*)d_in[4];
    const float* beta       = (const float*)d_in[5];
    const float* rmean      = (const float*)d_in[6];
    const float* rvar       = (const float*)d_in[7];
    float* out = (float*)d_out;

    const int N = in_sizes[0] / (MPTS * 4);

    pfn_precompute<<<1, 64>>>(W, gamma, beta, rmean, rvar);

    int blocks = (N + PPB - 1) / PPB;
    pfn_main<<<blocks, PPB * 32>>>((const float4*)features, num_points,
                                   (const int4*)coors, out, N);
}